// round 14
// baseline (speedup 1.0000x reference)
#include <cuda_runtime.h>
#include <cuda_bf16.h>
#include <cuda_fp16.h>
#include <math.h>
#include <stdint.h>

// Problem constants (fixed shapes from setup_inputs)
#define BB   32
#define NN   1568
#define NN0  3136
#define NT   784
#define CIN  256
#define COUT 512
#define HH   56
#define WW   56
#define H2   28
#define W2   28
#define HW   (HH*WW)     // 3136
#define P2   (H2*W2)     // 784
#define MM   (BB*NT)     // 25088

// ---------------- scratch (device globals; no allocations allowed) -------------
__device__ __half g_map [(size_t)BB*HW*CIN];  // token2map sums, fp16 (atomic f16x2 adds)
__device__ float g_cnt [BB*HW];               // scatter counts
__device__ float g_comb[(size_t)BB*NT*CIN];   // combined numerator (skip + back), UNNORMALIZED, fp32
__device__ float g_den [BB*NT];               // sum of agg_weight_t per target token
__device__ __half g_conv[(size_t)BB*P2*CIN];  // depthwise conv output, fp16 storage (fp32 math)
__device__ float g_stats1[2*CIN];
__device__ float g_stats2[2*COUT];
__device__ float g_wT  [CIN*COUT];            // BN1-folded weights, [K=Cin][N=Cout]
__device__ float g_cst [COUT];                // per-out-channel constant from BN1 bias

// ---------------- helpers ------------------------------------------------------

__device__ __forceinline__ void red4(float* addr, float a, float b, float c, float d) {
    asm volatile("red.global.add.v4.f32 [%0], {%1,%2,%3,%4};"
                 :: "l"(addr), "f"(a), "f"(b), "f"(c), "f"(d) : "memory");
}

__device__ __forceinline__ void redh2(__half* addr, uint32_t h2) {
    asm volatile("red.global.add.noftz.f16x2 [%0], %1;"
                 :: "l"(addr), "r"(h2) : "memory");
}

__device__ __forceinline__ uint32_t f2tf32(float x) {
    uint32_t u;
    asm("cvt.rna.tf32.f32 %0, %1;" : "=r"(u) : "f"(x));
    return u;
}

__device__ __forceinline__ int pix_index(float lx, float ly, int Hs, int Ws) {
    // match jnp: clip(loc,-1,1)*0.5+0.5, then round(t*(dim-1)) with round-half-even
    float tx = __fadd_rn(__fmul_rn(fminf(fmaxf(lx, -1.f), 1.f), 0.5f), 0.5f);
    float ty = __fadd_rn(__fmul_rn(fminf(fmaxf(ly, -1.f), 1.f), 0.5f), 0.5f);
    int ix = (int)rintf(__fmul_rn(tx, (float)(Ws - 1)));
    int iy = (int)rintf(__fmul_rn(ty, (float)(Hs - 1)));
    return iy * Ws + ix;
}

// ---------------- kernels ------------------------------------------------------

__global__ void k_zero() {
    int idx = blockIdx.x * blockDim.x + threadIdx.x;
    int stride = gridDim.x * blockDim.x;
    float4 z = make_float4(0.f, 0.f, 0.f, 0.f);
    // g_map: half array, 16 bytes = 8 halves per float4 store
    for (int i = idx; i < (int)((size_t)BB*HW*CIN/8); i += stride) ((float4*)g_map)[i]  = z;
    for (int i = idx; i < BB*HW/4;                    i += stride) ((float4*)g_cnt)[i]  = z;
    for (int i = idx; i < (int)((size_t)BB*NT*CIN/4); i += stride) ((float4*)g_comb)[i] = z;
    for (int i = idx; i < BB*NT/4;                    i += stride) ((float4*)g_den)[i]  = z;
    if (idx < 2*CIN)  g_stats1[idx] = 0.f;
    if (idx < 2*COUT) g_stats2[idx] = 0.f;
}

// Fused: token2map scatter (fp16 atomics) + skip-path (fp32) + cnt/den
// warp per (b,n0) row: 32 lanes x 2 float4 = 256 channels
__global__ void k_scatter(const float* __restrict__ x, const float* __restrict__ loc,
                          const int* __restrict__ ia, const int* __restrict__ iat,
                          const float* __restrict__ wt, const float* __restrict__ skipw) {
    int gw   = blockIdx.x * 8 + (threadIdx.x >> 5);   // row id in [0, B*N0)
    int lane = threadIdx.x & 31;
    int b = gw / NN0;
    float lx = loc[2*gw], ly = loc[2*gw+1];
    int p = pix_index(lx, ly, HH, WW);
    int s = ia[gw], t = iat[gw];
    float w = wt[gw];
    const float4* xr  = (const float4*)(x + ((size_t)b*NN + s)*CIN);
    const float4* sw4 = (const float4*)skipw;
    __half* mp = g_map + ((size_t)b*HW + p)*CIN;
    float*  cp = g_comb + ((size_t)b*NT + t)*CIN;
    #pragma unroll
    for (int q = 0; q < 2; q++) {
        int i = lane + q*32;
        float4 v  = xr[i];
        float4 sw = sw4[i];
        __half2 h0 = __floats2half2_rn(v.x, v.y);
        __half2 h1 = __floats2half2_rn(v.z, v.w);
        redh2(mp + i*4,     *reinterpret_cast<uint32_t*>(&h0));
        redh2(mp + i*4 + 2, *reinterpret_cast<uint32_t*>(&h1));
        red4(cp + i*4, w*sw.x*v.x, w*sw.y*v.y, w*sw.z*v.z, w*sw.w*v.w);
    }
    if (lane == 0) {
        atomicAdd(&g_cnt[b*HW + p], 1.f);
        atomicAdd(&g_den[b*NT + t], w);
    }
}

// Depthwise 3x3 stride 2 pad 1, /(cnt+eps) folded per tap.
// 2x2 output tile per block from a 5x5 input window. grid (196, B), 256 thr
// fp32 accumulate, fp16 store.
__global__ __launch_bounds__(256) void k_conv(const float* __restrict__ dw) {
    int b = blockIdx.y;
    int ty = blockIdx.x / 14, tx = blockIdx.x % 14;
    int oy0 = ty * 2, ox0 = tx * 2;
    __shared__ float inv[25];
    __shared__ int   poff[25];
    int tid = threadIdx.x;
    if (tid < 25) {
        int r = tid / 5, c = tid % 5;
        int iy = oy0*2 - 1 + r, ix = ox0*2 - 1 + c;
        if (iy >= 0 && iy < HH && ix >= 0 && ix < WW) {
            int p = iy*WW + ix;
            poff[tid] = p;
            inv[tid]  = 1.f / (g_cnt[b*HW + p] + 1e-6f);
        } else { poff[tid] = -1; inv[tid] = 0.f; }
    }
    __syncthreads();
    const __half* mb = g_map + (size_t)b*HW*CIN;
    float wv[9];
    #pragma unroll
    for (int k = 0; k < 9; k++) wv[k] = dw[tid*9 + k];
    float acc00 = 0.f, acc01 = 0.f, acc10 = 0.f, acc11 = 0.f;
    #pragma unroll
    for (int r = 0; r < 5; r++) {
        #pragma unroll
        for (int cc = 0; cc < 5; cc++) {
            int p = poff[r*5 + cc];
            float val = (p >= 0) ? __half2float(mb[(size_t)p*CIN + tid]) * inv[r*5 + cc] : 0.f;
            // output (dy,dx) uses tap (ky,kx) = (r-2dy, cc-2dx) when in [0,2]
            #pragma unroll
            for (int dy = 0; dy < 2; dy++) {
                int ky = r - 2*dy;
                if (ky < 0 || ky > 2) continue;
                #pragma unroll
                for (int dx = 0; dx < 2; dx++) {
                    int kx = cc - 2*dx;
                    if (kx < 0 || kx > 2) continue;
                    float wtap = wv[ky*3 + kx];
                    if (dy == 0 && dx == 0) acc00 += val * wtap;
                    if (dy == 0 && dx == 1) acc01 += val * wtap;
                    if (dy == 1 && dx == 0) acc10 += val * wtap;
                    if (dy == 1 && dx == 1) acc11 += val * wtap;
                }
            }
        }
    }
    size_t base = ((size_t)b*P2 + oy0*W2 + ox0)*CIN + tid;
    g_conv[base]                      = __float2half(acc00);
    g_conv[base + CIN]                = __float2half(acc01);
    g_conv[base + (size_t)W2*CIN]     = __float2half(acc10);
    g_conv[base + (size_t)(W2+1)*CIN] = __float2half(acc11);
}

// map2token: gather fp16 conv row (one 512B pass: 8 halves/lane), fp32 red4 into comb
__global__ void k_gather(const float* __restrict__ loc, const int* __restrict__ iat,
                         const float* __restrict__ wt) {
    int gw   = blockIdx.x * 8 + (threadIdx.x >> 5);
    int lane = threadIdx.x & 31;
    int b = gw / NN0;
    float lx = loc[2*gw], ly = loc[2*gw+1];
    int p = pix_index(lx, ly, H2, W2);
    int t = iat[gw];
    float w = wt[gw];
    const uint4* src = (const uint4*)(g_conv + ((size_t)b*P2 + p)*CIN);
    float* cp = g_comb + ((size_t)b*NT + t)*CIN;
    uint4 u = src[lane];                       // 8 halves: channels lane*8 .. lane*8+7
    __half2 h0 = *reinterpret_cast<__half2*>(&u.x);
    __half2 h1 = *reinterpret_cast<__half2*>(&u.y);
    __half2 h2 = *reinterpret_cast<__half2*>(&u.z);
    __half2 h3 = *reinterpret_cast<__half2*>(&u.w);
    float2 f0 = __half22float2(h0);
    float2 f1 = __half22float2(h1);
    float2 f2 = __half22float2(h2);
    float2 f3 = __half22float2(h3);
    int c = lane * 8;
    red4(cp + c,     w*f0.x, w*f0.y, w*f1.x, w*f1.y);
    red4(cp + c + 4, w*f2.x, w*f2.y, w*f3.x, w*f3.y);
}

// BN1 stats only (no write): v = comb/(den+eps), accumulate per-channel sum/sumsq
__global__ void k_fin1() {
    int c = threadIdx.x;                 // 256
    float s = 0.f, s2 = 0.f;
    for (int r = blockIdx.x; r < MM; r += gridDim.x) {
        float inv = 1.f / (g_den[r] + 1e-6f);
        float v = g_comb[(size_t)r*CIN + c] * inv;
        s += v; s2 += v * v;
    }
    atomicAdd(&g_stats1[c],        s);
    atomicAdd(&g_stats1[CIN + c],  s2);
}

// fold BN1 (scale/bias computed inline from stats) into weights ([K][N]);
// reduce bias*w into per-o constant. grid 512 x 256 thr
__global__ void k_prepw(const float* __restrict__ cw, const float* __restrict__ gamma,
                        const float* __restrict__ beta) {
    int o = blockIdx.x;                 // 512
    int c = threadIdx.x;                // 256
    float mean = g_stats1[c] / (float)MM;
    float var  = g_stats1[CIN + c] / (float)MM - mean * mean;
    float a    = gamma[c] * rsqrtf(var + 1e-5f);
    float bias = beta[c] - mean * a;
    float wv = cw[o*CIN + c];
    g_wT[c*COUT + o] = wv * a;
    __shared__ float red[256];
    red[c] = wv * bias;
    __syncthreads();
    for (int off = 128; off; off >>= 1) {
        if (c < off) red[c] += red[c + off];
        __syncthreads();
    }
    if (c == 0) g_cst[o] = red[0];
}

// ---------------- tf32 tensor-core GEMM + row-scale + fused BN2 stats ----------
// C[25088,512] = (A[25088,256] * inv_den[row]) @ wT[256,512] + cst
// block 128x128, BK=32; 8 warps as 4(m) x 2(n), warp tile 32x64  (R9-proven)
// sden IS LOAD-BEARING: g_comb holds the unnormalized numerator.

#define GBM 128
#define GBN 128
#define GBK 32

__device__ __forceinline__ void mma_tf32(float* c, const uint32_t* a,
                                         uint32_t b0, uint32_t b1) {
    asm volatile(
        "mma.sync.aligned.m16n8k8.row.col.f32.tf32.tf32.f32 "
        "{%0,%1,%2,%3}, {%4,%5,%6,%7}, {%8,%9}, {%0,%1,%2,%3};"
        : "+f"(c[0]), "+f"(c[1]), "+f"(c[2]), "+f"(c[3])
        : "r"(a[0]), "r"(a[1]), "r"(a[2]), "r"(a[3]), "r"(b0), "r"(b1));
}

__global__ __launch_bounds__(256, 1) void k_gemm(float* __restrict__ C) {
    __shared__ float As[GBM][36];
    __shared__ float Bs[GBN][36];
    __shared__ float sden[GBM];
    int tid  = threadIdx.x;
    int lane = tid & 31, warp = tid >> 5;
    int wm = warp & 3, wn = warp >> 2;
    int rowBase = blockIdx.y * GBM, colBase = blockIdx.x * GBN;

    if (tid < GBM) sden[tid] = 1.f / (g_den[rowBase + tid] + 1e-6f);

    int arow = tid >> 3, acol = (tid & 7) << 2;
    int bk = lane, bn = warp << 4;

    const float* Ag = g_comb + (size_t)rowBase * CIN;
    const float* Bg = g_wT + colBase;

    float4 ra[4], rb[4];
    #pragma unroll
    for (int q = 0; q < 4; q++)
        ra[q] = *(const float4*)(Ag + (size_t)(arow + 32*q)*CIN + acol);
    #pragma unroll
    for (int t = 0; t < 4; t++)
        rb[t] = *(const float4*)(Bg + (size_t)bk*COUT + bn + t*4);

    float acc[2][8][4] = {};
    __syncthreads();   // sden ready

    #pragma unroll 1
    for (int c = 0; c < CIN/GBK; c++) {
        // commit prefetched chunk to smem (row-scaled, tf32-rounded)
        #pragma unroll
        for (int q = 0; q < 4; q++) {
            float4 v = ra[q];
            float sc = sden[arow + 32*q];
            uint4 u = make_uint4(f2tf32(v.x*sc), f2tf32(v.y*sc),
                                 f2tf32(v.z*sc), f2tf32(v.w*sc));
            *(uint4*)&As[arow + 32*q][acol] = u;
        }
        #pragma unroll
        for (int t = 0; t < 4; t++) {
            float4 v = rb[t];
            int n0 = bn + t*4;
            Bs[n0+0][bk] = __uint_as_float(f2tf32(v.x));
            Bs[n0+1][bk] = __uint_as_float(f2tf32(v.y));
            Bs[n0+2][bk] = __uint_as_float(f2tf32(v.z));
            Bs[n0+3][bk] = __uint_as_float(f2tf32(v.w));
        }
        __syncthreads();

        if (c + 1 < CIN/GBK) {
            int k0 = (c + 1) * GBK;
            #pragma unroll
            for (int q = 0; q < 4; q++)
                ra[q] = *(const float4*)(Ag + (size_t)(arow + 32*q)*CIN + k0 + acol);
            #pragma unroll
            for (int t = 0; t < 4; t++)
                rb[t] = *(const float4*)(Bg + (size_t)(k0 + bk)*COUT + bn + t*4);
        }

        int rA = wm*32 + (lane >> 2);
        #pragma unroll
        for (int kk = 0; kk < 4; kk++) {
            int kc = kk*8 + (lane & 3);
            uint32_t a[2][4];
            #pragma unroll
            for (int i = 0; i < 2; i++) {
                a[i][0] = __float_as_uint(As[rA + i*16    ][kc]);
                a[i][1] = __float_as_uint(As[rA + i*16 + 8][kc]);
                a[i][2] = __float_as_uint(As[rA + i*16    ][kc + 4]);
                a[i][3] = __float_as_uint(As[rA + i*16 + 8][kc + 4]);
            }
            #pragma unroll
            for (int j = 0; j < 8; j++) {
                int rB = wn*64 + j*8 + (lane >> 2);
                uint32_t b0 = __float_as_uint(Bs[rB][kc]);
                uint32_t b1 = __float_as_uint(Bs[rB][kc + 4]);
                #pragma unroll
                for (int i = 0; i < 2; i++)
                    mma_tf32(acc[i][j], a[i], b0, b1);
            }
        }
        __syncthreads();
    }

    // epilogue: + cst, store, accumulate per-column BN2 stats
    float s[8][2], s2[8][2];
    #pragma unroll
    for (int j = 0; j < 8; j++) { s[j][0]=s[j][1]=s2[j][0]=s2[j][1]=0.f; }

    #pragma unroll
    for (int j = 0; j < 8; j++) {
        int col = colBase + wn*64 + j*8 + 2*(lane & 3);
        float2 cst2 = *(const float2*)&g_cst[col];
        #pragma unroll
        for (int i = 0; i < 2; i++) {
            int row0 = rowBase + wm*32 + i*16 + (lane >> 2);
            float z00 = acc[i][j][0] + cst2.x;
            float z01 = acc[i][j][1] + cst2.y;
            float z10 = acc[i][j][2] + cst2.x;
            float z11 = acc[i][j][3] + cst2.y;
            *(float2*)&C[(size_t)row0*COUT + col]       = make_float2(z00, z01);
            *(float2*)&C[(size_t)(row0 + 8)*COUT + col] = make_float2(z10, z11);
            s [j][0] += z00 + z10;         s [j][1] += z01 + z11;
            s2[j][0] += z00*z00 + z10*z10; s2[j][1] += z01*z01 + z11*z11;
        }
    }
    #pragma unroll
    for (int j = 0; j < 8; j++) {
        #pragma unroll
        for (int pr = 0; pr < 2; pr++) {
            float a = s[j][pr], b = s2[j][pr];
            #pragma unroll
            for (int off = 4; off <= 16; off <<= 1) {
                a += __shfl_xor_sync(0xffffffffu, a, off);
                b += __shfl_xor_sync(0xffffffffu, b, off);
            }
            if ((lane >> 2) == 0) {
                int col = colBase + wn*64 + j*8 + 2*(lane & 3) + pr;
                atomicAdd(&g_stats2[col],        a);
                atomicAdd(&g_stats2[COUT + col], b);
            }
        }
    }
}

// fused BN2-prep + affine + ReLU: each block recomputes ab2 into smem (identical
// deterministic values per block), then applies to its strided slice of z
__global__ void k_final(float* __restrict__ z, const float* __restrict__ gamma,
                        const float* __restrict__ beta) {
    __shared__ float sa[COUT], sb[COUT];
    int tid = threadIdx.x;
    #pragma unroll
    for (int q = 0; q < 2; q++) {
        int c = tid + q*256;
        float mean = g_stats2[c] / (float)MM;
        float var  = g_stats2[COUT + c] / (float)MM - mean * mean;
        float a = gamma[c] * rsqrtf(var + 1e-5f);
        sa[c] = a;
        sb[c] = beta[c] - mean * a;
    }
    __syncthreads();
    int idx = blockIdx.x * blockDim.x + tid;
    int stride = gridDim.x * blockDim.x;
    int n4 = MM * COUT / 4;
    for (int i = idx; i < n4; i += stride) {
        float4 v = ((float4*)z)[i];
        int o = (i * 4) & (COUT - 1);
        float4 a = *(const float4*)&sa[o];
        float4 b = *(const float4*)&sb[o];
        v.x = fmaxf(fmaf(a.x, v.x, b.x), 0.f);
        v.y = fmaxf(fmaf(a.y, v.y, b.y), 0.f);
        v.z = fmaxf(fmaf(a.z, v.z, b.z), 0.f);
        v.w = fmaxf(fmaf(a.w, v.w, b.w), 0.f);
        ((float4*)z)[i] = v;
    }
}

// ---------------- host launcher ------------------------------------------------

extern "C" void kernel_launch(void* const* d_in, const int* in_sizes, int n_in,
                              void* d_out, int out_size) {
    const float *x = nullptr, *loc = nullptr, *wt = nullptr;
    const float *dw = nullptr, *skipw = nullptr, *cw = nullptr;
    const float *g1 = nullptr, *b1 = nullptr, *g2 = nullptr, *b2 = nullptr;
    const int *ia = nullptr, *iat = nullptr;
    int c100352 = 0, c256 = 0, c512 = 0;
    for (int i = 0; i < n_in; i++) {
        int s = in_sizes[i];
        const void* p = d_in[i];
        if      (s == 12845056) x   = (const float*)p;
        else if (s == 200704)   loc = (const float*)p;
        else if (s == 100352) {
            if      (c100352 == 0) ia  = (const int*)p;     // idx_agg
            else if (c100352 == 1) { /* agg_weight: unused */ }
            else if (c100352 == 2) iat = (const int*)p;     // idx_agg_t
            else                   wt  = (const float*)p;   // agg_weight_t
            c100352++;
        }
        else if (s == 2304)   dw = (const float*)p;
        else if (s == 131072) cw = (const float*)p;
        else if (s == 256) {
            if      (c256 == 0) skipw = (const float*)p;
            else if (c256 == 1) g1    = (const float*)p;
            else                b1    = (const float*)p;
            c256++;
        }
        else if (s == 512) {
            if (c512 == 0) g2 = (const float*)p;
            else           b2 = (const float*)p;
            c512++;
        }
    }

    float* out = (float*)d_out;

    k_zero<<<1184, 256>>>();
    k_scatter<<<BB*NN0/8, 256>>>(x, loc, ia, iat, wt, skipw);
    k_conv<<<dim3(196, BB), 256>>>(dw);
    k_gather<<<BB*NN0/8, 256>>>(loc, iat, wt);
    k_fin1<<<1024, 256>>>();
    k_prepw<<<COUT, CIN>>>(cw, g1, b1);
    k_gemm<<<dim3(COUT/GBN, MM/GBM), 256>>>(out);
    k_final<<<1184, 256>>>(out, g2, b2);
}

// round 15
// speedup vs baseline: 1.0418x; 1.0418x over previous
#include <cuda_runtime.h>
#include <cuda_bf16.h>
#include <cuda_fp16.h>
#include <math.h>
#include <stdint.h>

// Problem constants (fixed shapes from setup_inputs)
#define BB   32
#define NN   1568
#define NN0  3136
#define NT   784
#define CIN  256
#define COUT 512
#define HH   56
#define WW   56
#define H2   28
#define W2   28
#define HW   (HH*WW)     // 3136
#define P2   (H2*W2)     // 784
#define MM   (BB*NT)     // 25088

// ---------------- scratch (device globals; no allocations allowed) -------------
__device__ __half g_map [(size_t)BB*HW*CIN];  // token2map sums, fp16 (atomic f16x2 adds)
__device__ float g_cnt [BB*HW];               // scatter counts
__device__ float g_comb[(size_t)BB*NT*CIN];   // combined numerator (skip + back), UNNORMALIZED, fp32
__device__ float g_den [BB*NT];               // sum of agg_weight_t per target token
__device__ __half g_conv[(size_t)BB*P2*CIN];  // depthwise conv output, fp16 storage (fp32 math)
__device__ float g_stats1[2*CIN];
__device__ float g_stats2[2*COUT];
__device__ float g_wT  [CIN*COUT];            // BN1-folded weights, [K=Cin][N=Cout]
__device__ float g_cst [COUT];                // per-out-channel constant from BN1 bias

// ---------------- helpers ------------------------------------------------------

__device__ __forceinline__ void red4(float* addr, float a, float b, float c, float d) {
    asm volatile("red.global.add.v4.f32 [%0], {%1,%2,%3,%4};"
                 :: "l"(addr), "f"(a), "f"(b), "f"(c), "f"(d) : "memory");
}

__device__ __forceinline__ void redh2(__half* addr, uint32_t h2) {
    asm volatile("red.global.add.noftz.f16x2 [%0], %1;"
                 :: "l"(addr), "r"(h2) : "memory");
}

__device__ __forceinline__ uint32_t f2tf32(float x) {
    uint32_t u;
    asm("cvt.rna.tf32.f32 %0, %1;" : "=r"(u) : "f"(x));
    return u;
}

__device__ __forceinline__ int pix_index(float lx, float ly, int Hs, int Ws) {
    // match jnp: clip(loc,-1,1)*0.5+0.5, then round(t*(dim-1)) with round-half-even
    float tx = __fadd_rn(__fmul_rn(fminf(fmaxf(lx, -1.f), 1.f), 0.5f), 0.5f);
    float ty = __fadd_rn(__fmul_rn(fminf(fmaxf(ly, -1.f), 1.f), 0.5f), 0.5f);
    int ix = (int)rintf(__fmul_rn(tx, (float)(Ws - 1)));
    int iy = (int)rintf(__fmul_rn(ty, (float)(Hs - 1)));
    return iy * Ws + ix;
}

// ---------------- kernels ------------------------------------------------------

__global__ void k_zero() {
    int idx = blockIdx.x * blockDim.x + threadIdx.x;
    int stride = gridDim.x * blockDim.x;
    float4 z = make_float4(0.f, 0.f, 0.f, 0.f);
    // g_map: half array, 16 bytes = 8 halves per float4 store
    for (int i = idx; i < (int)((size_t)BB*HW*CIN/8); i += stride) ((float4*)g_map)[i]  = z;
    for (int i = idx; i < BB*HW/4;                    i += stride) ((float4*)g_cnt)[i]  = z;
    for (int i = idx; i < (int)((size_t)BB*NT*CIN/4); i += stride) ((float4*)g_comb)[i] = z;
    for (int i = idx; i < BB*NT/4;                    i += stride) ((float4*)g_den)[i]  = z;
    if (idx < 2*CIN)  g_stats1[idx] = 0.f;
    if (idx < 2*COUT) g_stats2[idx] = 0.f;
}

// Fused: token2map scatter (fp16 atomics) + skip-path (fp32) + cnt/den
// warp per (b,n0) row: 32 lanes x 2 float4 = 256 channels
__global__ void k_scatter(const float* __restrict__ x, const float* __restrict__ loc,
                          const int* __restrict__ ia, const int* __restrict__ iat,
                          const float* __restrict__ wt, const float* __restrict__ skipw) {
    int gw   = blockIdx.x * 8 + (threadIdx.x >> 5);   // row id in [0, B*N0)
    int lane = threadIdx.x & 31;
    int b = gw / NN0;
    float lx = loc[2*gw], ly = loc[2*gw+1];
    int p = pix_index(lx, ly, HH, WW);
    int s = ia[gw], t = iat[gw];
    float w = wt[gw];
    const float4* xr  = (const float4*)(x + ((size_t)b*NN + s)*CIN);
    const float4* sw4 = (const float4*)skipw;
    __half* mp = g_map + ((size_t)b*HW + p)*CIN;
    float*  cp = g_comb + ((size_t)b*NT + t)*CIN;
    #pragma unroll
    for (int q = 0; q < 2; q++) {
        int i = lane + q*32;
        float4 v  = xr[i];
        float4 sw = sw4[i];
        __half2 h0 = __floats2half2_rn(v.x, v.y);
        __half2 h1 = __floats2half2_rn(v.z, v.w);
        redh2(mp + i*4,     *reinterpret_cast<uint32_t*>(&h0));
        redh2(mp + i*4 + 2, *reinterpret_cast<uint32_t*>(&h1));
        red4(cp + i*4, w*sw.x*v.x, w*sw.y*v.y, w*sw.z*v.z, w*sw.w*v.w);
    }
    if (lane == 0) {
        atomicAdd(&g_cnt[b*HW + p], 1.f);
        atomicAdd(&g_den[b*NT + t], w);
    }
}

// Depthwise 3x3 stride 2 pad 1, /(cnt+eps) folded per tap.
// 2x2 output tile per block from a 5x5 input window. grid (196, B), 256 thr
// fp32 accumulate, fp16 store.
__global__ __launch_bounds__(256) void k_conv(const float* __restrict__ dw) {
    int b = blockIdx.y;
    int ty = blockIdx.x / 14, tx = blockIdx.x % 14;
    int oy0 = ty * 2, ox0 = tx * 2;
    __shared__ float inv[25];
    __shared__ int   poff[25];
    int tid = threadIdx.x;
    if (tid < 25) {
        int r = tid / 5, c = tid % 5;
        int iy = oy0*2 - 1 + r, ix = ox0*2 - 1 + c;
        if (iy >= 0 && iy < HH && ix >= 0 && ix < WW) {
            int p = iy*WW + ix;
            poff[tid] = p;
            inv[tid]  = 1.f / (g_cnt[b*HW + p] + 1e-6f);
        } else { poff[tid] = -1; inv[tid] = 0.f; }
    }
    __syncthreads();
    const __half* mb = g_map + (size_t)b*HW*CIN;
    float wv[9];
    #pragma unroll
    for (int k = 0; k < 9; k++) wv[k] = dw[tid*9 + k];
    float acc00 = 0.f, acc01 = 0.f, acc10 = 0.f, acc11 = 0.f;
    #pragma unroll
    for (int r = 0; r < 5; r++) {
        #pragma unroll
        for (int cc = 0; cc < 5; cc++) {
            int p = poff[r*5 + cc];
            float val = (p >= 0) ? __half2float(mb[(size_t)p*CIN + tid]) * inv[r*5 + cc] : 0.f;
            // output (dy,dx) uses tap (ky,kx) = (r-2dy, cc-2dx) when in [0,2]
            #pragma unroll
            for (int dy = 0; dy < 2; dy++) {
                int ky = r - 2*dy;
                if (ky < 0 || ky > 2) continue;
                #pragma unroll
                for (int dx = 0; dx < 2; dx++) {
                    int kx = cc - 2*dx;
                    if (kx < 0 || kx > 2) continue;
                    float wtap = wv[ky*3 + kx];
                    if (dy == 0 && dx == 0) acc00 += val * wtap;
                    if (dy == 0 && dx == 1) acc01 += val * wtap;
                    if (dy == 1 && dx == 0) acc10 += val * wtap;
                    if (dy == 1 && dx == 1) acc11 += val * wtap;
                }
            }
        }
    }
    size_t base = ((size_t)b*P2 + oy0*W2 + ox0)*CIN + tid;
    g_conv[base]                      = __float2half(acc00);
    g_conv[base + CIN]                = __float2half(acc01);
    g_conv[base + (size_t)W2*CIN]     = __float2half(acc10);
    g_conv[base + (size_t)(W2+1)*CIN] = __float2half(acc11);
}

// map2token: gather fp16 conv row via 2 independent uint2 loads (256B/warp each,
// MLP=2), red4 writes contiguous across warp (R13 pattern: lane -> c=lane*4, 128+lane*4)
__global__ void k_gather(const float* __restrict__ loc, const int* __restrict__ iat,
                         const float* __restrict__ wt) {
    int gw   = blockIdx.x * 8 + (threadIdx.x >> 5);
    int lane = threadIdx.x & 31;
    int b = gw / NN0;
    float lx = loc[2*gw], ly = loc[2*gw+1];
    int p = pix_index(lx, ly, H2, W2);
    int t = iat[gw];
    float w = wt[gw];
    const uint2* src = (const uint2*)(g_conv + ((size_t)b*P2 + p)*CIN);
    float* cp = g_comb + ((size_t)b*NT + t)*CIN;
    uint2 u0 = src[lane];        // channels lane*4 .. lane*4+3
    uint2 u1 = src[lane + 32];   // channels 128+lane*4 .. +3
    __half2 a0 = *reinterpret_cast<__half2*>(&u0.x);
    __half2 a1 = *reinterpret_cast<__half2*>(&u0.y);
    __half2 b0 = *reinterpret_cast<__half2*>(&u1.x);
    __half2 b1 = *reinterpret_cast<__half2*>(&u1.y);
    float2 f0 = __half22float2(a0);
    float2 f1 = __half22float2(a1);
    float2 f2 = __half22float2(b0);
    float2 f3 = __half22float2(b1);
    red4(cp + lane*4,       w*f0.x, w*f0.y, w*f1.x, w*f1.y);
    red4(cp + 128 + lane*4, w*f2.x, w*f2.y, w*f3.x, w*f3.y);
}

// BN1 stats only (no write): v = comb/(den+eps), accumulate per-channel sum/sumsq
__global__ void k_fin1() {
    int c = threadIdx.x;                 // 256
    float s = 0.f, s2 = 0.f;
    for (int r = blockIdx.x; r < MM; r += gridDim.x) {
        float inv = 1.f / (g_den[r] + 1e-6f);
        float v = g_comb[(size_t)r*CIN + c] * inv;
        s += v; s2 += v * v;
    }
    atomicAdd(&g_stats1[c],        s);
    atomicAdd(&g_stats1[CIN + c],  s2);
}

// fold BN1 (scale/bias computed inline from stats) into weights ([K][N]);
// reduce bias*w into per-o constant. grid 512 x 256 thr
__global__ void k_prepw(const float* __restrict__ cw, const float* __restrict__ gamma,
                        const float* __restrict__ beta) {
    int o = blockIdx.x;                 // 512
    int c = threadIdx.x;                // 256
    float mean = g_stats1[c] / (float)MM;
    float var  = g_stats1[CIN + c] / (float)MM - mean * mean;
    float a    = gamma[c] * rsqrtf(var + 1e-5f);
    float bias = beta[c] - mean * a;
    float wv = cw[o*CIN + c];
    g_wT[c*COUT + o] = wv * a;
    __shared__ float red[256];
    red[c] = wv * bias;
    __syncthreads();
    for (int off = 128; off; off >>= 1) {
        if (c < off) red[c] += red[c + off];
        __syncthreads();
    }
    if (c == 0) g_cst[o] = red[0];
}

// ---------------- tf32 tensor-core GEMM + row-scale + fused BN2 stats ----------
// C[25088,512] = (A[25088,256] * inv_den[row]) @ wT[256,512] + cst
// block 128x128, BK=32; 8 warps as 4(m) x 2(n), warp tile 32x64  (R9-proven)
// sden IS LOAD-BEARING: g_comb holds the unnormalized numerator.

#define GBM 128
#define GBN 128
#define GBK 32

__device__ __forceinline__ void mma_tf32(float* c, const uint32_t* a,
                                         uint32_t b0, uint32_t b1) {
    asm volatile(
        "mma.sync.aligned.m16n8k8.row.col.f32.tf32.tf32.f32 "
        "{%0,%1,%2,%3}, {%4,%5,%6,%7}, {%8,%9}, {%0,%1,%2,%3};"
        : "+f"(c[0]), "+f"(c[1]), "+f"(c[2]), "+f"(c[3])
        : "r"(a[0]), "r"(a[1]), "r"(a[2]), "r"(a[3]), "r"(b0), "r"(b1));
}

__global__ __launch_bounds__(256, 1) void k_gemm(float* __restrict__ C) {
    __shared__ float As[GBM][36];
    __shared__ float Bs[GBN][36];
    __shared__ float sden[GBM];
    int tid  = threadIdx.x;
    int lane = tid & 31, warp = tid >> 5;
    int wm = warp & 3, wn = warp >> 2;
    int rowBase = blockIdx.y * GBM, colBase = blockIdx.x * GBN;

    if (tid < GBM) sden[tid] = 1.f / (g_den[rowBase + tid] + 1e-6f);

    int arow = tid >> 3, acol = (tid & 7) << 2;
    int bk = lane, bn = warp << 4;

    const float* Ag = g_comb + (size_t)rowBase * CIN;
    const float* Bg = g_wT + colBase;

    float4 ra[4], rb[4];
    #pragma unroll
    for (int q = 0; q < 4; q++)
        ra[q] = *(const float4*)(Ag + (size_t)(arow + 32*q)*CIN + acol);
    #pragma unroll
    for (int t = 0; t < 4; t++)
        rb[t] = *(const float4*)(Bg + (size_t)bk*COUT + bn + t*4);

    float acc[2][8][4] = {};
    __syncthreads();   // sden ready

    #pragma unroll 1
    for (int c = 0; c < CIN/GBK; c++) {
        // commit prefetched chunk to smem (row-scaled, tf32-rounded)
        #pragma unroll
        for (int q = 0; q < 4; q++) {
            float4 v = ra[q];
            float sc = sden[arow + 32*q];
            uint4 u = make_uint4(f2tf32(v.x*sc), f2tf32(v.y*sc),
                                 f2tf32(v.z*sc), f2tf32(v.w*sc));
            *(uint4*)&As[arow + 32*q][acol] = u;
        }
        #pragma unroll
        for (int t = 0; t < 4; t++) {
            float4 v = rb[t];
            int n0 = bn + t*4;
            Bs[n0+0][bk] = __uint_as_float(f2tf32(v.x));
            Bs[n0+1][bk] = __uint_as_float(f2tf32(v.y));
            Bs[n0+2][bk] = __uint_as_float(f2tf32(v.z));
            Bs[n0+3][bk] = __uint_as_float(f2tf32(v.w));
        }
        __syncthreads();

        if (c + 1 < CIN/GBK) {
            int k0 = (c + 1) * GBK;
            #pragma unroll
            for (int q = 0; q < 4; q++)
                ra[q] = *(const float4*)(Ag + (size_t)(arow + 32*q)*CIN + k0 + acol);
            #pragma unroll
            for (int t = 0; t < 4; t++)
                rb[t] = *(const float4*)(Bg + (size_t)(k0 + bk)*COUT + bn + t*4);
        }

        int rA = wm*32 + (lane >> 2);
        #pragma unroll
        for (int kk = 0; kk < 4; kk++) {
            int kc = kk*8 + (lane & 3);
            uint32_t a[2][4];
            #pragma unroll
            for (int i = 0; i < 2; i++) {
                a[i][0] = __float_as_uint(As[rA + i*16    ][kc]);
                a[i][1] = __float_as_uint(As[rA + i*16 + 8][kc]);
                a[i][2] = __float_as_uint(As[rA + i*16    ][kc + 4]);
                a[i][3] = __float_as_uint(As[rA + i*16 + 8][kc + 4]);
            }
            #pragma unroll
            for (int j = 0; j < 8; j++) {
                int rB = wn*64 + j*8 + (lane >> 2);
                uint32_t b0 = __float_as_uint(Bs[rB][kc]);
                uint32_t b1 = __float_as_uint(Bs[rB][kc + 4]);
                #pragma unroll
                for (int i = 0; i < 2; i++)
                    mma_tf32(acc[i][j], a[i], b0, b1);
            }
        }
        __syncthreads();
    }

    // epilogue: + cst, store, accumulate per-column BN2 stats
    float s[8][2], s2[8][2];
    #pragma unroll
    for (int j = 0; j < 8; j++) { s[j][0]=s[j][1]=s2[j][0]=s2[j][1]=0.f; }

    #pragma unroll
    for (int j = 0; j < 8; j++) {
        int col = colBase + wn*64 + j*8 + 2*(lane & 3);
        float2 cst2 = *(const float2*)&g_cst[col];
        #pragma unroll
        for (int i = 0; i < 2; i++) {
            int row0 = rowBase + wm*32 + i*16 + (lane >> 2);
            float z00 = acc[i][j][0] + cst2.x;
            float z01 = acc[i][j][1] + cst2.y;
            float z10 = acc[i][j][2] + cst2.x;
            float z11 = acc[i][j][3] + cst2.y;
            *(float2*)&C[(size_t)row0*COUT + col]       = make_float2(z00, z01);
            *(float2*)&C[(size_t)(row0 + 8)*COUT + col] = make_float2(z10, z11);
            s [j][0] += z00 + z10;         s [j][1] += z01 + z11;
            s2[j][0] += z00*z00 + z10*z10; s2[j][1] += z01*z01 + z11*z11;
        }
    }
    #pragma unroll
    for (int j = 0; j < 8; j++) {
        #pragma unroll
        for (int pr = 0; pr < 2; pr++) {
            float a = s[j][pr], b = s2[j][pr];
            #pragma unroll
            for (int off = 4; off <= 16; off <<= 1) {
                a += __shfl_xor_sync(0xffffffffu, a, off);
                b += __shfl_xor_sync(0xffffffffu, b, off);
            }
            if ((lane >> 2) == 0) {
                int col = colBase + wn*64 + j*8 + 2*(lane & 3) + pr;
                atomicAdd(&g_stats2[col],        a);
                atomicAdd(&g_stats2[COUT + col], b);
            }
        }
    }
}

// fused BN2-prep + affine + ReLU: each block recomputes ab2 into smem (identical
// deterministic values per block), then applies to its strided slice of z
__global__ void k_final(float* __restrict__ z, const float* __restrict__ gamma,
                        const float* __restrict__ beta) {
    __shared__ float sa[COUT], sb[COUT];
    int tid = threadIdx.x;
    #pragma unroll
    for (int q = 0; q < 2; q++) {
        int c = tid + q*256;
        float mean = g_stats2[c] / (float)MM;
        float var  = g_stats2[COUT + c] / (float)MM - mean * mean;
        float a = gamma[c] * rsqrtf(var + 1e-5f);
        sa[c] = a;
        sb[c] = beta[c] - mean * a;
    }
    __syncthreads();
    int idx = blockIdx.x * blockDim.x + tid;
    int stride = gridDim.x * blockDim.x;
    int n4 = MM * COUT / 4;
    for (int i = idx; i < n4; i += stride) {
        float4 v = ((float4*)z)[i];
        int o = (i * 4) & (COUT - 1);
        float4 a = *(const float4*)&sa[o];
        float4 b = *(const float4*)&sb[o];
        v.x = fmaxf(fmaf(a.x, v.x, b.x), 0.f);
        v.y = fmaxf(fmaf(a.y, v.y, b.y), 0.f);
        v.z = fmaxf(fmaf(a.z, v.z, b.z), 0.f);
        v.w = fmaxf(fmaf(a.w, v.w, b.w), 0.f);
        ((float4*)z)[i] = v;
    }
}

// ---------------- host launcher ------------------------------------------------

extern "C" void kernel_launch(void* const* d_in, const int* in_sizes, int n_in,
                              void* d_out, int out_size) {
    const float *x = nullptr, *loc = nullptr, *wt = nullptr;
    const float *dw = nullptr, *skipw = nullptr, *cw = nullptr;
    const float *g1 = nullptr, *b1 = nullptr, *g2 = nullptr, *b2 = nullptr;
    const int *ia = nullptr, *iat = nullptr;
    int c100352 = 0, c256 = 0, c512 = 0;
    for (int i = 0; i < n_in; i++) {
        int s = in_sizes[i];
        const void* p = d_in[i];
        if      (s == 12845056) x   = (const float*)p;
        else if (s == 200704)   loc = (const float*)p;
        else if (s == 100352) {
            if      (c100352 == 0) ia  = (const int*)p;     // idx_agg
            else if (c100352 == 1) { /* agg_weight: unused */ }
            else if (c100352 == 2) iat = (const int*)p;     // idx_agg_t
            else                   wt  = (const float*)p;   // agg_weight_t
            c100352++;
        }
        else if (s == 2304)   dw = (const float*)p;
        else if (s == 131072) cw = (const float*)p;
        else if (s == 256) {
            if      (c256 == 0) skipw = (const float*)p;
            else if (c256 == 1) g1    = (const float*)p;
            else                b1    = (const float*)p;
            c256++;
        }
        else if (s == 512) {
            if (c512 == 0) g2 = (const float*)p;
            else           b2 = (const float*)p;
            c512++;
        }
    }

    float* out = (float*)d_out;

    k_zero<<<1184, 256>>>();
    k_scatter<<<BB*NN0/8, 256>>>(x, loc, ia, iat, wt, skipw);
    k_conv<<<dim3(196, BB), 256>>>(dw);
    k_gather<<<BB*NN0/8, 256>>>(loc, iat, wt);
    k_fin1<<<1024, 256>>>();
    k_prepw<<<COUT, CIN>>>(cw, g1, b1);
    k_gemm<<<dim3(COUT/GBN, MM/GBM), 256>>>(out);
    k_final<<<1184, 256>>>(out, g2, b2);
}

// round 16
// speedup vs baseline: 1.0993x; 1.0552x over previous
#include <cuda_runtime.h>
#include <cuda_bf16.h>
#include <cuda_fp16.h>
#include <math.h>
#include <stdint.h>

// Problem constants (fixed shapes from setup_inputs)
#define BB   32
#define NN   1568
#define NN0  3136
#define NT   784
#define CIN  256
#define COUT 512
#define HH   56
#define WW   56
#define H2   28
#define W2   28
#define HW   (HH*WW)     // 3136
#define P2   (H2*W2)     // 784
#define MM   (BB*NT)     // 25088

// ---------------- scratch (device globals; no allocations allowed) -------------
__device__ __half g_map [(size_t)BB*HW*CIN];  // token2map sums, fp16 (atomic f16x2 adds)
__device__ float g_cnt [BB*HW];               // scatter counts
__device__ float g_comb[(size_t)BB*NT*CIN];   // combined numerator (skip + back), UNNORMALIZED, fp32
__device__ float g_den [BB*NT];               // sum of agg_weight_t per target token
__device__ __half g_conv[(size_t)BB*P2*CIN];  // depthwise conv output, fp16 storage (fp32 math)
__device__ float g_stats1[2*CIN];
__device__ float g_stats2[2*COUT];
__device__ float g_wT  [CIN*COUT];            // BN1-folded weights, [K=Cin][N=Cout]
__device__ float g_cst [COUT];                // per-out-channel constant from BN1 bias

// ---------------- helpers ------------------------------------------------------

__device__ __forceinline__ void red4(float* addr, float a, float b, float c, float d) {
    asm volatile("red.global.add.v4.f32 [%0], {%1,%2,%3,%4};"
                 :: "l"(addr), "f"(a), "f"(b), "f"(c), "f"(d) : "memory");
}

__device__ __forceinline__ void redh2(__half* addr, uint32_t h2) {
    asm volatile("red.global.add.noftz.f16x2 [%0], %1;"
                 :: "l"(addr), "r"(h2) : "memory");
}

__device__ __forceinline__ int pix_index(float lx, float ly, int Hs, int Ws) {
    // match jnp: clip(loc,-1,1)*0.5+0.5, then round(t*(dim-1)) with round-half-even
    float tx = __fadd_rn(__fmul_rn(fminf(fmaxf(lx, -1.f), 1.f), 0.5f), 0.5f);
    float ty = __fadd_rn(__fmul_rn(fminf(fmaxf(ly, -1.f), 1.f), 0.5f), 0.5f);
    int ix = (int)rintf(__fmul_rn(tx, (float)(Ws - 1)));
    int iy = (int)rintf(__fmul_rn(ty, (float)(Hs - 1)));
    return iy * Ws + ix;
}

// ---------------- kernels ------------------------------------------------------

__global__ void k_zero() {
    int idx = blockIdx.x * blockDim.x + threadIdx.x;
    int stride = gridDim.x * blockDim.x;
    float4 z = make_float4(0.f, 0.f, 0.f, 0.f);
    // g_map: half array, 16 bytes = 8 halves per float4 store
    for (int i = idx; i < (int)((size_t)BB*HW*CIN/8); i += stride) ((float4*)g_map)[i]  = z;
    for (int i = idx; i < BB*HW/4;                    i += stride) ((float4*)g_cnt)[i]  = z;
    for (int i = idx; i < (int)((size_t)BB*NT*CIN/4); i += stride) ((float4*)g_comb)[i] = z;
    for (int i = idx; i < BB*NT/4;                    i += stride) ((float4*)g_den)[i]  = z;
    if (idx < 2*CIN)  g_stats1[idx] = 0.f;
    if (idx < 2*COUT) g_stats2[idx] = 0.f;
}

// Fused: token2map scatter (fp16 atomics) + skip-path (fp32) + cnt/den
// warp per (b,n0) row: 32 lanes x 2 float4 = 256 channels
__global__ void k_scatter(const float* __restrict__ x, const float* __restrict__ loc,
                          const int* __restrict__ ia, const int* __restrict__ iat,
                          const float* __restrict__ wt, const float* __restrict__ skipw) {
    int gw   = blockIdx.x * 8 + (threadIdx.x >> 5);   // row id in [0, B*N0)
    int lane = threadIdx.x & 31;
    int b = gw / NN0;
    float lx = loc[2*gw], ly = loc[2*gw+1];
    int p = pix_index(lx, ly, HH, WW);
    int s = ia[gw], t = iat[gw];
    float w = wt[gw];
    const float4* xr  = (const float4*)(x + ((size_t)b*NN + s)*CIN);
    const float4* sw4 = (const float4*)skipw;
    __half* mp = g_map + ((size_t)b*HW + p)*CIN;
    float*  cp = g_comb + ((size_t)b*NT + t)*CIN;
    #pragma unroll
    for (int q = 0; q < 2; q++) {
        int i = lane + q*32;
        float4 v  = xr[i];
        float4 sw = sw4[i];
        __half2 h0 = __floats2half2_rn(v.x, v.y);
        __half2 h1 = __floats2half2_rn(v.z, v.w);
        redh2(mp + i*4,     *reinterpret_cast<uint32_t*>(&h0));
        redh2(mp + i*4 + 2, *reinterpret_cast<uint32_t*>(&h1));
        red4(cp + i*4, w*sw.x*v.x, w*sw.y*v.y, w*sw.z*v.z, w*sw.w*v.w);
    }
    if (lane == 0) {
        atomicAdd(&g_cnt[b*HW + p], 1.f);
        atomicAdd(&g_den[b*NT + t], w);
    }
}

// Depthwise 3x3 stride 2 pad 1, /(cnt+eps) folded per tap.
// 2x2 output tile per block from a 5x5 input window. grid (196, B), 256 thr
// fp32 accumulate, fp16 store.
__global__ __launch_bounds__(256) void k_conv(const float* __restrict__ dw) {
    int b = blockIdx.y;
    int ty = blockIdx.x / 14, tx = blockIdx.x % 14;
    int oy0 = ty * 2, ox0 = tx * 2;
    __shared__ float inv[25];
    __shared__ int   poff[25];
    int tid = threadIdx.x;
    if (tid < 25) {
        int r = tid / 5, c = tid % 5;
        int iy = oy0*2 - 1 + r, ix = ox0*2 - 1 + c;
        if (iy >= 0 && iy < HH && ix >= 0 && ix < WW) {
            int p = iy*WW + ix;
            poff[tid] = p;
            inv[tid]  = 1.f / (g_cnt[b*HW + p] + 1e-6f);
        } else { poff[tid] = -1; inv[tid] = 0.f; }
    }
    __syncthreads();
    const __half* mb = g_map + (size_t)b*HW*CIN;
    float wv[9];
    #pragma unroll
    for (int k = 0; k < 9; k++) wv[k] = dw[tid*9 + k];
    float acc00 = 0.f, acc01 = 0.f, acc10 = 0.f, acc11 = 0.f;
    #pragma unroll
    for (int r = 0; r < 5; r++) {
        #pragma unroll
        for (int cc = 0; cc < 5; cc++) {
            int p = poff[r*5 + cc];
            float val = (p >= 0) ? __half2float(mb[(size_t)p*CIN + tid]) * inv[r*5 + cc] : 0.f;
            // output (dy,dx) uses tap (ky,kx) = (r-2dy, cc-2dx) when in [0,2]
            #pragma unroll
            for (int dy = 0; dy < 2; dy++) {
                int ky = r - 2*dy;
                if (ky < 0 || ky > 2) continue;
                #pragma unroll
                for (int dx = 0; dx < 2; dx++) {
                    int kx = cc - 2*dx;
                    if (kx < 0 || kx > 2) continue;
                    float wtap = wv[ky*3 + kx];
                    if (dy == 0 && dx == 0) acc00 += val * wtap;
                    if (dy == 0 && dx == 1) acc01 += val * wtap;
                    if (dy == 1 && dx == 0) acc10 += val * wtap;
                    if (dy == 1 && dx == 1) acc11 += val * wtap;
                }
            }
        }
    }
    size_t base = ((size_t)b*P2 + oy0*W2 + ox0)*CIN + tid;
    g_conv[base]                      = __float2half(acc00);
    g_conv[base + CIN]                = __float2half(acc01);
    g_conv[base + (size_t)W2*CIN]     = __float2half(acc10);
    g_conv[base + (size_t)(W2+1)*CIN] = __float2half(acc11);
}

// map2token: gather fp16 conv row via 2 independent uint2 loads (256B/warp each,
// MLP=2), red4 writes contiguous across warp (lane -> c=lane*4, 128+lane*4)
__global__ void k_gather(const float* __restrict__ loc, const int* __restrict__ iat,
                         const float* __restrict__ wt) {
    int gw   = blockIdx.x * 8 + (threadIdx.x >> 5);
    int lane = threadIdx.x & 31;
    int b = gw / NN0;
    float lx = loc[2*gw], ly = loc[2*gw+1];
    int p = pix_index(lx, ly, H2, W2);
    int t = iat[gw];
    float w = wt[gw];
    const uint2* src = (const uint2*)(g_conv + ((size_t)b*P2 + p)*CIN);
    float* cp = g_comb + ((size_t)b*NT + t)*CIN;
    uint2 u0 = src[lane];        // channels lane*4 .. lane*4+3
    uint2 u1 = src[lane + 32];   // channels 128+lane*4 .. +3
    __half2 a0 = *reinterpret_cast<__half2*>(&u0.x);
    __half2 a1 = *reinterpret_cast<__half2*>(&u0.y);
    __half2 b0 = *reinterpret_cast<__half2*>(&u1.x);
    __half2 b1 = *reinterpret_cast<__half2*>(&u1.y);
    float2 f0 = __half22float2(a0);
    float2 f1 = __half22float2(a1);
    float2 f2 = __half22float2(b0);
    float2 f3 = __half22float2(b1);
    red4(cp + lane*4,       w*f0.x, w*f0.y, w*f1.x, w*f1.y);
    red4(cp + 128 + lane*4, w*f2.x, w*f2.y, w*f3.x, w*f3.y);
}

// BN1 stats only (no write): v = comb/(den+eps), accumulate per-channel sum/sumsq
__global__ void k_fin1() {
    int c = threadIdx.x;                 // 256
    float s = 0.f, s2 = 0.f;
    for (int r = blockIdx.x; r < MM; r += gridDim.x) {
        float inv = 1.f / (g_den[r] + 1e-6f);
        float v = g_comb[(size_t)r*CIN + c] * inv;
        s += v; s2 += v * v;
    }
    atomicAdd(&g_stats1[c],        s);
    atomicAdd(&g_stats1[CIN + c],  s2);
}

// fold BN1 (scale/bias computed inline from stats) into weights ([K][N]);
// reduce bias*w into per-o constant. grid 512 x 256 thr
__global__ void k_prepw(const float* __restrict__ cw, const float* __restrict__ gamma,
                        const float* __restrict__ beta) {
    int o = blockIdx.x;                 // 512
    int c = threadIdx.x;                // 256
    float mean = g_stats1[c] / (float)MM;
    float var  = g_stats1[CIN + c] / (float)MM - mean * mean;
    float a    = gamma[c] * rsqrtf(var + 1e-5f);
    float bias = beta[c] - mean * a;
    float wv = cw[o*CIN + c];
    g_wT[c*COUT + o] = wv * a;
    __shared__ float red[256];
    red[c] = wv * bias;
    __syncthreads();
    for (int off = 128; off; off >>= 1) {
        if (c < off) red[c] += red[c + off];
        __syncthreads();
    }
    if (c == 0) g_cst[o] = red[0];
}

// ---------------- fp16 tensor-core GEMM + row-scale + fused BN2 stats ----------
// C[25088,512] = (A[25088,256] * inv_den[row]) @ wT[256,512] + cst
// block 128x128, BK=32; 8 warps as 4(m) x 2(n), warp tile 32x64
// mma m16n8k16 f16.f16.f32 — fp16 shares tf32's 11-bit significand: same error,
// 2x per-instruction throughput. C-fragment layout identical to m16n8k8 (epilogue
// unchanged). sden IS LOAD-BEARING: g_comb holds the unnormalized numerator.

#define GBM 128
#define GBN 128
#define GBK 32
#define BKH 40     // padded smem stride in halves (80B rows: conflict-free)

__device__ __forceinline__ void mma_f16(float* c, const uint32_t* a,
                                        uint32_t b0, uint32_t b1) {
    asm volatile(
        "mma.sync.aligned.m16n8k16.row.col.f32.f16.f16.f32 "
        "{%0,%1,%2,%3}, {%4,%5,%6,%7}, {%8,%9}, {%0,%1,%2,%3};"
        : "+f"(c[0]), "+f"(c[1]), "+f"(c[2]), "+f"(c[3])
        : "r"(a[0]), "r"(a[1]), "r"(a[2]), "r"(a[3]), "r"(b0), "r"(b1));
}

__global__ __launch_bounds__(256, 1) void k_gemm(float* __restrict__ C) {
    __shared__ __half As[GBM][BKH];
    __shared__ __half Bs[GBN][BKH];
    __shared__ float sden[GBM];
    int tid  = threadIdx.x;
    int lane = tid & 31, warp = tid >> 5;
    int wm = warp & 3, wn = warp >> 2;
    int rowBase = blockIdx.y * GBM, colBase = blockIdx.x * GBN;

    if (tid < GBM) sden[tid] = 1.f / (g_den[rowBase + tid] + 1e-6f);

    int arow = tid >> 3, acol = (tid & 7) << 2;
    int bk = lane, bn = warp << 4;

    const float* Ag = g_comb + (size_t)rowBase * CIN;
    const float* Bg = g_wT + colBase;

    float4 ra[4], rb[4];
    #pragma unroll
    for (int q = 0; q < 4; q++)
        ra[q] = *(const float4*)(Ag + (size_t)(arow + 32*q)*CIN + acol);
    #pragma unroll
    for (int t = 0; t < 4; t++)
        rb[t] = *(const float4*)(Bg + (size_t)bk*COUT + bn + t*4);

    float acc[2][8][4] = {};
    __syncthreads();   // sden ready

    #pragma unroll 1
    for (int c = 0; c < CIN/GBK; c++) {
        // commit prefetched chunk to smem (row-scaled, fp16)
        #pragma unroll
        for (int q = 0; q < 4; q++) {
            float4 v = ra[q];
            float sc = sden[arow + 32*q];
            __half2 h0 = __floats2half2_rn(v.x*sc, v.y*sc);
            __half2 h1 = __floats2half2_rn(v.z*sc, v.w*sc);
            uint2 u = make_uint2(*reinterpret_cast<uint32_t*>(&h0),
                                 *reinterpret_cast<uint32_t*>(&h1));
            *(uint2*)&As[arow + 32*q][acol] = u;
        }
        #pragma unroll
        for (int t = 0; t < 4; t++) {
            float4 v = rb[t];
            int n0 = bn + t*4;
            Bs[n0+0][bk] = __float2half(v.x);
            Bs[n0+1][bk] = __float2half(v.y);
            Bs[n0+2][bk] = __float2half(v.z);
            Bs[n0+3][bk] = __float2half(v.w);
        }
        __syncthreads();

        if (c + 1 < CIN/GBK) {
            int k0 = (c + 1) * GBK;
            #pragma unroll
            for (int q = 0; q < 4; q++)
                ra[q] = *(const float4*)(Ag + (size_t)(arow + 32*q)*CIN + k0 + acol);
            #pragma unroll
            for (int t = 0; t < 4; t++)
                rb[t] = *(const float4*)(Bg + (size_t)(k0 + bk)*COUT + bn + t*4);
        }

        int rA = wm*32 + (lane >> 2);
        #pragma unroll
        for (int ks = 0; ks < 2; ks++) {       // two k16 steps per BK=32 chunk
            int kc = ks*16 + 2*(lane & 3);
            uint32_t a[2][4];
            #pragma unroll
            for (int i = 0; i < 2; i++) {
                a[i][0] = *(const uint32_t*)&As[rA + i*16    ][kc];
                a[i][1] = *(const uint32_t*)&As[rA + i*16 + 8][kc];
                a[i][2] = *(const uint32_t*)&As[rA + i*16    ][kc + 8];
                a[i][3] = *(const uint32_t*)&As[rA + i*16 + 8][kc + 8];
            }
            #pragma unroll
            for (int j = 0; j < 8; j++) {
                int rB = wn*64 + j*8 + (lane >> 2);
                uint32_t b0 = *(const uint32_t*)&Bs[rB][kc];
                uint32_t b1 = *(const uint32_t*)&Bs[rB][kc + 8];
                #pragma unroll
                for (int i = 0; i < 2; i++)
                    mma_f16(acc[i][j], a[i], b0, b1);
            }
        }
        __syncthreads();
    }

    // epilogue: + cst, store, accumulate per-column BN2 stats
    float s[8][2], s2[8][2];
    #pragma unroll
    for (int j = 0; j < 8; j++) { s[j][0]=s[j][1]=s2[j][0]=s2[j][1]=0.f; }

    #pragma unroll
    for (int j = 0; j < 8; j++) {
        int col = colBase + wn*64 + j*8 + 2*(lane & 3);
        float2 cst2 = *(const float2*)&g_cst[col];
        #pragma unroll
        for (int i = 0; i < 2; i++) {
            int row0 = rowBase + wm*32 + i*16 + (lane >> 2);
            float z00 = acc[i][j][0] + cst2.x;
            float z01 = acc[i][j][1] + cst2.y;
            float z10 = acc[i][j][2] + cst2.x;
            float z11 = acc[i][j][3] + cst2.y;
            *(float2*)&C[(size_t)row0*COUT + col]       = make_float2(z00, z01);
            *(float2*)&C[(size_t)(row0 + 8)*COUT + col] = make_float2(z10, z11);
            s [j][0] += z00 + z10;         s [j][1] += z01 + z11;
            s2[j][0] += z00*z00 + z10*z10; s2[j][1] += z01*z01 + z11*z11;
        }
    }
    #pragma unroll
    for (int j = 0; j < 8; j++) {
        #pragma unroll
        for (int pr = 0; pr < 2; pr++) {
            float a = s[j][pr], b = s2[j][pr];
            #pragma unroll
            for (int off = 4; off <= 16; off <<= 1) {
                a += __shfl_xor_sync(0xffffffffu, a, off);
                b += __shfl_xor_sync(0xffffffffu, b, off);
            }
            if ((lane >> 2) == 0) {
                int col = colBase + wn*64 + j*8 + 2*(lane & 3) + pr;
                atomicAdd(&g_stats2[col],        a);
                atomicAdd(&g_stats2[COUT + col], b);
            }
        }
    }
}

// fused BN2-prep + affine + ReLU: each block recomputes ab2 into smem (identical
// deterministic values per block), then applies to its strided slice of z
__global__ void k_final(float* __restrict__ z, const float* __restrict__ gamma,
                        const float* __restrict__ beta) {
    __shared__ float sa[COUT], sb[COUT];
    int tid = threadIdx.x;
    #pragma unroll
    for (int q = 0; q < 2; q++) {
        int c = tid + q*256;
        float mean = g_stats2[c] / (float)MM;
        float var  = g_stats2[COUT + c] / (float)MM - mean * mean;
        float a = gamma[c] * rsqrtf(var + 1e-5f);
        sa[c] = a;
        sb[c] = beta[c] - mean * a;
    }
    __syncthreads();
    int idx = blockIdx.x * blockDim.x + tid;
    int stride = gridDim.x * blockDim.x;
    int n4 = MM * COUT / 4;
    for (int i = idx; i < n4; i += stride) {
        float4 v = ((float4*)z)[i];
        int o = (i * 4) & (COUT - 1);
        float4 a = *(const float4*)&sa[o];
        float4 b = *(const float4*)&sb[o];
        v.x = fmaxf(fmaf(a.x, v.x, b.x), 0.f);
        v.y = fmaxf(fmaf(a.y, v.y, b.y), 0.f);
        v.z = fmaxf(fmaf(a.z, v.z, b.z), 0.f);
        v.w = fmaxf(fmaf(a.w, v.w, b.w), 0.f);
        ((float4*)z)[i] = v;
    }
}

// ---------------- host launcher ------------------------------------------------

extern "C" void kernel_launch(void* const* d_in, const int* in_sizes, int n_in,
                              void* d_out, int out_size) {
    const float *x = nullptr, *loc = nullptr, *wt = nullptr;
    const float *dw = nullptr, *skipw = nullptr, *cw = nullptr;
    const float *g1 = nullptr, *b1 = nullptr, *g2 = nullptr, *b2 = nullptr;
    const int *ia = nullptr, *iat = nullptr;
    int c100352 = 0, c256 = 0, c512 = 0;
    for (int i = 0; i < n_in; i++) {
        int s = in_sizes[i];
        const void* p = d_in[i];
        if      (s == 12845056) x   = (const float*)p;
        else if (s == 200704)   loc = (const float*)p;
        else if (s == 100352) {
            if      (c100352 == 0) ia  = (const int*)p;     // idx_agg
            else if (c100352 == 1) { /* agg_weight: unused */ }
            else if (c100352 == 2) iat = (const int*)p;     // idx_agg_t
            else                   wt  = (const float*)p;   // agg_weight_t
            c100352++;
        }
        else if (s == 2304)   dw = (const float*)p;
        else if (s == 131072) cw = (const float*)p;
        else if (s == 256) {
            if      (c256 == 0) skipw = (const float*)p;
            else if (c256 == 1) g1    = (const float*)p;
            else                b1    = (const float*)p;
            c256++;
        }
        else if (s == 512) {
            if (c512 == 0) g2 = (const float*)p;
            else           b2 = (const float*)p;
            c512++;
        }
    }

    float* out = (float*)d_out;

    k_zero<<<1184, 256>>>();
    k_scatter<<<BB*NN0/8, 256>>>(x, loc, ia, iat, wt, skipw);
    k_conv<<<dim3(196, BB), 256>>>(dw);
    k_gather<<<BB*NN0/8, 256>>>(loc, iat, wt);
    k_fin1<<<1024, 256>>>();
    k_prepw<<<COUT, CIN>>>(cw, g1, b1);
    k_gemm<<<dim3(COUT/GBN, MM/GBM), 256>>>(out);
    k_final<<<1184, 256>>>(out, g2, b2);
}

// round 17
// speedup vs baseline: 1.1075x; 1.0074x over previous
#include <cuda_runtime.h>
#include <cuda_bf16.h>
#include <cuda_fp16.h>
#include <math.h>
#include <stdint.h>

// Problem constants (fixed shapes from setup_inputs)
#define BB   32
#define NN   1568
#define NN0  3136
#define NT   784
#define CIN  256
#define COUT 512
#define HH   56
#define WW   56
#define H2   28
#define W2   28
#define HW   (HH*WW)     // 3136
#define P2   (H2*W2)     // 784
#define MM   (BB*NT)     // 25088

// ---------------- scratch (device globals; no allocations allowed) -------------
__device__ __half g_map [(size_t)BB*HW*CIN];  // token2map sums, fp16 (atomic f16x2 adds)
__device__ float g_cnt [BB*HW];               // scatter counts
__device__ float g_comb[(size_t)BB*NT*CIN];   // combined numerator (skip + back), UNNORMALIZED, fp32
__device__ float g_den [BB*NT];               // sum of agg_weight_t per target token
__device__ __half g_conv[(size_t)BB*P2*CIN];  // depthwise conv output, fp16 storage (fp32 math)
__device__ float g_stats1[2*CIN];
__device__ float g_stats2[2*COUT];
__device__ float g_wT  [CIN*COUT];            // BN1-folded weights, [K=Cin][N=Cout]
__device__ float g_cst [COUT];                // per-out-channel constant from BN1 bias

// ---------------- helpers ------------------------------------------------------

__device__ __forceinline__ void red4(float* addr, float a, float b, float c, float d) {
    asm volatile("red.global.add.v4.f32 [%0], {%1,%2,%3,%4};"
                 :: "l"(addr), "f"(a), "f"(b), "f"(c), "f"(d) : "memory");
}

__device__ __forceinline__ void redh2(__half* addr, uint32_t h2) {
    asm volatile("red.global.add.noftz.f16x2 [%0], %1;"
                 :: "l"(addr), "r"(h2) : "memory");
}

__device__ __forceinline__ void ldsm_x4(uint32_t* r, uint32_t saddr) {
    asm volatile("ldmatrix.sync.aligned.m8n8.x4.shared.b16 {%0,%1,%2,%3}, [%4];"
                 : "=r"(r[0]), "=r"(r[1]), "=r"(r[2]), "=r"(r[3]) : "r"(saddr));
}

__device__ __forceinline__ int pix_index(float lx, float ly, int Hs, int Ws) {
    // match jnp: clip(loc,-1,1)*0.5+0.5, then round(t*(dim-1)) with round-half-even
    float tx = __fadd_rn(__fmul_rn(fminf(fmaxf(lx, -1.f), 1.f), 0.5f), 0.5f);
    float ty = __fadd_rn(__fmul_rn(fminf(fmaxf(ly, -1.f), 1.f), 0.5f), 0.5f);
    int ix = (int)rintf(__fmul_rn(tx, (float)(Ws - 1)));
    int iy = (int)rintf(__fmul_rn(ty, (float)(Hs - 1)));
    return iy * Ws + ix;
}

// ---------------- kernels ------------------------------------------------------

__global__ void k_zero() {
    int idx = blockIdx.x * blockDim.x + threadIdx.x;
    int stride = gridDim.x * blockDim.x;
    float4 z = make_float4(0.f, 0.f, 0.f, 0.f);
    // g_map: half array, 16 bytes = 8 halves per float4 store
    for (int i = idx; i < (int)((size_t)BB*HW*CIN/8); i += stride) ((float4*)g_map)[i]  = z;
    for (int i = idx; i < BB*HW/4;                    i += stride) ((float4*)g_cnt)[i]  = z;
    for (int i = idx; i < (int)((size_t)BB*NT*CIN/4); i += stride) ((float4*)g_comb)[i] = z;
    for (int i = idx; i < BB*NT/4;                    i += stride) ((float4*)g_den)[i]  = z;
    if (idx < 2*CIN)  g_stats1[idx] = 0.f;
    if (idx < 2*COUT) g_stats2[idx] = 0.f;
}

// Fused: token2map scatter (fp16 atomics) + skip-path (fp32) + cnt/den
// warp per (b,n0) row: 32 lanes x 2 float4 = 256 channels
__global__ void k_scatter(const float* __restrict__ x, const float* __restrict__ loc,
                          const int* __restrict__ ia, const int* __restrict__ iat,
                          const float* __restrict__ wt, const float* __restrict__ skipw) {
    int gw   = blockIdx.x * 8 + (threadIdx.x >> 5);   // row id in [0, B*N0)
    int lane = threadIdx.x & 31;
    int b = gw / NN0;
    float lx = loc[2*gw], ly = loc[2*gw+1];
    int p = pix_index(lx, ly, HH, WW);
    int s = ia[gw], t = iat[gw];
    float w = wt[gw];
    const float4* xr  = (const float4*)(x + ((size_t)b*NN + s)*CIN);
    const float4* sw4 = (const float4*)skipw;
    __half* mp = g_map + ((size_t)b*HW + p)*CIN;
    float*  cp = g_comb + ((size_t)b*NT + t)*CIN;
    #pragma unroll
    for (int q = 0; q < 2; q++) {
        int i = lane + q*32;
        float4 v  = xr[i];
        float4 sw = sw4[i];
        __half2 h0 = __floats2half2_rn(v.x, v.y);
        __half2 h1 = __floats2half2_rn(v.z, v.w);
        redh2(mp + i*4,     *reinterpret_cast<uint32_t*>(&h0));
        redh2(mp + i*4 + 2, *reinterpret_cast<uint32_t*>(&h1));
        red4(cp + i*4, w*sw.x*v.x, w*sw.y*v.y, w*sw.z*v.z, w*sw.w*v.w);
    }
    if (lane == 0) {
        atomicAdd(&g_cnt[b*HW + p], 1.f);
        atomicAdd(&g_den[b*NT + t], w);
    }
}

// Depthwise 3x3 stride 2 pad 1, /(cnt+eps) folded per tap.
// 2x2 output tile per block from a 5x5 input window. grid (196, B), 256 thr
// fp32 accumulate, fp16 store.
__global__ __launch_bounds__(256) void k_conv(const float* __restrict__ dw) {
    int b = blockIdx.y;
    int ty = blockIdx.x / 14, tx = blockIdx.x % 14;
    int oy0 = ty * 2, ox0 = tx * 2;
    __shared__ float inv[25];
    __shared__ int   poff[25];
    int tid = threadIdx.x;
    if (tid < 25) {
        int r = tid / 5, c = tid % 5;
        int iy = oy0*2 - 1 + r, ix = ox0*2 - 1 + c;
        if (iy >= 0 && iy < HH && ix >= 0 && ix < WW) {
            int p = iy*WW + ix;
            poff[tid] = p;
            inv[tid]  = 1.f / (g_cnt[b*HW + p] + 1e-6f);
        } else { poff[tid] = -1; inv[tid] = 0.f; }
    }
    __syncthreads();
    const __half* mb = g_map + (size_t)b*HW*CIN;
    float wv[9];
    #pragma unroll
    for (int k = 0; k < 9; k++) wv[k] = dw[tid*9 + k];
    float acc00 = 0.f, acc01 = 0.f, acc10 = 0.f, acc11 = 0.f;
    #pragma unroll
    for (int r = 0; r < 5; r++) {
        #pragma unroll
        for (int cc = 0; cc < 5; cc++) {
            int p = poff[r*5 + cc];
            float val = (p >= 0) ? __half2float(mb[(size_t)p*CIN + tid]) * inv[r*5 + cc] : 0.f;
            // output (dy,dx) uses tap (ky,kx) = (r-2dy, cc-2dx) when in [0,2]
            #pragma unroll
            for (int dy = 0; dy < 2; dy++) {
                int ky = r - 2*dy;
                if (ky < 0 || ky > 2) continue;
                #pragma unroll
                for (int dx = 0; dx < 2; dx++) {
                    int kx = cc - 2*dx;
                    if (kx < 0 || kx > 2) continue;
                    float wtap = wv[ky*3 + kx];
                    if (dy == 0 && dx == 0) acc00 += val * wtap;
                    if (dy == 0 && dx == 1) acc01 += val * wtap;
                    if (dy == 1 && dx == 0) acc10 += val * wtap;
                    if (dy == 1 && dx == 1) acc11 += val * wtap;
                }
            }
        }
    }
    size_t base = ((size_t)b*P2 + oy0*W2 + ox0)*CIN + tid;
    g_conv[base]                      = __float2half(acc00);
    g_conv[base + CIN]                = __float2half(acc01);
    g_conv[base + (size_t)W2*CIN]     = __float2half(acc10);
    g_conv[base + (size_t)(W2+1)*CIN] = __float2half(acc11);
}

// map2token: gather fp16 conv row via 2 independent uint2 loads (256B/warp each,
// MLP=2), red4 writes contiguous across warp (lane -> c=lane*4, 128+lane*4)
__global__ void k_gather(const float* __restrict__ loc, const int* __restrict__ iat,
                         const float* __restrict__ wt) {
    int gw   = blockIdx.x * 8 + (threadIdx.x >> 5);
    int lane = threadIdx.x & 31;
    int b = gw / NN0;
    float lx = loc[2*gw], ly = loc[2*gw+1];
    int p = pix_index(lx, ly, H2, W2);
    int t = iat[gw];
    float w = wt[gw];
    const uint2* src = (const uint2*)(g_conv + ((size_t)b*P2 + p)*CIN);
    float* cp = g_comb + ((size_t)b*NT + t)*CIN;
    uint2 u0 = src[lane];        // channels lane*4 .. lane*4+3
    uint2 u1 = src[lane + 32];   // channels 128+lane*4 .. +3
    __half2 a0 = *reinterpret_cast<__half2*>(&u0.x);
    __half2 a1 = *reinterpret_cast<__half2*>(&u0.y);
    __half2 b0 = *reinterpret_cast<__half2*>(&u1.x);
    __half2 b1 = *reinterpret_cast<__half2*>(&u1.y);
    float2 f0 = __half22float2(a0);
    float2 f1 = __half22float2(a1);
    float2 f2 = __half22float2(b0);
    float2 f3 = __half22float2(b1);
    red4(cp + lane*4,       w*f0.x, w*f0.y, w*f1.x, w*f1.y);
    red4(cp + 128 + lane*4, w*f2.x, w*f2.y, w*f3.x, w*f3.y);
}

// BN1 stats only (no write): v = comb/(den+eps), accumulate per-channel sum/sumsq
__global__ void k_fin1() {
    int c = threadIdx.x;                 // 256
    float s = 0.f, s2 = 0.f;
    for (int r = blockIdx.x; r < MM; r += gridDim.x) {
        float inv = 1.f / (g_den[r] + 1e-6f);
        float v = g_comb[(size_t)r*CIN + c] * inv;
        s += v; s2 += v * v;
    }
    atomicAdd(&g_stats1[c],        s);
    atomicAdd(&g_stats1[CIN + c],  s2);
}

// fold BN1 (scale/bias computed inline from stats) into weights ([K][N]);
// reduce bias*w into per-o constant. grid 512 x 256 thr
__global__ void k_prepw(const float* __restrict__ cw, const float* __restrict__ gamma,
                        const float* __restrict__ beta) {
    int o = blockIdx.x;                 // 512
    int c = threadIdx.x;                // 256
    float mean = g_stats1[c] / (float)MM;
    float var  = g_stats1[CIN + c] / (float)MM - mean * mean;
    float a    = gamma[c] * rsqrtf(var + 1e-5f);
    float bias = beta[c] - mean * a;
    float wv = cw[o*CIN + c];
    g_wT[c*COUT + o] = wv * a;
    __shared__ float red[256];
    red[c] = wv * bias;
    __syncthreads();
    for (int off = 128; off; off >>= 1) {
        if (c < off) red[c] += red[c + off];
        __syncthreads();
    }
    if (c == 0) g_cst[o] = red[0];
}

// ---------------- fp16 tensor-core GEMM + row-scale + fused BN2 stats ----------
// C[25088,512] = (A[25088,256] * inv_den[row]) @ wT[256,512] + cst
// block 128x128, BK=32; 8 warps as 4(m) x 2(n), warp tile 32x64
// mma m16n8k16 f16.f16.f32, fragments loaded via ldmatrix.x4 (12 ldsm/chunk vs
// 48 scalar LDS). 80-byte padded rows: conflict-free, 16B-aligned.
// sden IS LOAD-BEARING: g_comb holds the unnormalized numerator.

#define GBM 128
#define GBN 128
#define GBK 32
#define BKH 40     // padded smem stride in halves (80B rows)

__device__ __forceinline__ void mma_f16(float* c, const uint32_t* a,
                                        uint32_t b0, uint32_t b1) {
    asm volatile(
        "mma.sync.aligned.m16n8k16.row.col.f32.f16.f16.f32 "
        "{%0,%1,%2,%3}, {%4,%5,%6,%7}, {%8,%9}, {%0,%1,%2,%3};"
        : "+f"(c[0]), "+f"(c[1]), "+f"(c[2]), "+f"(c[3])
        : "r"(a[0]), "r"(a[1]), "r"(a[2]), "r"(a[3]), "r"(b0), "r"(b1));
}

__global__ __launch_bounds__(256, 1) void k_gemm(float* __restrict__ C) {
    __shared__ __half As[GBM][BKH];
    __shared__ __half Bs[GBN][BKH];
    __shared__ float sden[GBM];
    int tid  = threadIdx.x;
    int lane = tid & 31, warp = tid >> 5;
    int wm = warp & 3, wn = warp >> 2;
    int rowBase = blockIdx.y * GBM, colBase = blockIdx.x * GBN;

    if (tid < GBM) sden[tid] = 1.f / (g_den[rowBase + tid] + 1e-6f);

    int arow = tid >> 3, acol = (tid & 7) << 2;
    int bk = lane, bn = warp << 4;

    const float* Ag = g_comb + (size_t)rowBase * CIN;
    const float* Bg = g_wT + colBase;

    uint32_t sA = (uint32_t)__cvta_generic_to_shared(&As[0][0]);
    uint32_t sB = (uint32_t)__cvta_generic_to_shared(&Bs[0][0]);
    // per-lane ldmatrix base addresses (byte offsets within tile added per use)
    uint32_t aAddrBase = sA + (uint32_t)(((wm*32 + (lane & 15))*BKH + (lane >> 4)*8) * 2);
    int bm = lane >> 3;                       // matrix index 0..3
    uint32_t bAddrBase = sB + (uint32_t)(((wn*64 + ((bm >> 1) << 3) + (lane & 7))*BKH
                                          + ((bm & 1) << 3)) * 2);

    float4 ra[4], rb[4];
    #pragma unroll
    for (int q = 0; q < 4; q++)
        ra[q] = *(const float4*)(Ag + (size_t)(arow + 32*q)*CIN + acol);
    #pragma unroll
    for (int t = 0; t < 4; t++)
        rb[t] = *(const float4*)(Bg + (size_t)bk*COUT + bn + t*4);

    float acc[2][8][4] = {};
    __syncthreads();   // sden ready

    #pragma unroll 1
    for (int c = 0; c < CIN/GBK; c++) {
        // commit prefetched chunk to smem (row-scaled, fp16)
        #pragma unroll
        for (int q = 0; q < 4; q++) {
            float4 v = ra[q];
            float sc = sden[arow + 32*q];
            __half2 h0 = __floats2half2_rn(v.x*sc, v.y*sc);
            __half2 h1 = __floats2half2_rn(v.z*sc, v.w*sc);
            uint2 u = make_uint2(*reinterpret_cast<uint32_t*>(&h0),
                                 *reinterpret_cast<uint32_t*>(&h1));
            *(uint2*)&As[arow + 32*q][acol] = u;
        }
        #pragma unroll
        for (int t = 0; t < 4; t++) {
            float4 v = rb[t];
            int n0 = bn + t*4;
            Bs[n0+0][bk] = __float2half(v.x);
            Bs[n0+1][bk] = __float2half(v.y);
            Bs[n0+2][bk] = __float2half(v.z);
            Bs[n0+3][bk] = __float2half(v.w);
        }
        __syncthreads();

        if (c + 1 < CIN/GBK) {
            int k0 = (c + 1) * GBK;
            #pragma unroll
            for (int q = 0; q < 4; q++)
                ra[q] = *(const float4*)(Ag + (size_t)(arow + 32*q)*CIN + k0 + acol);
            #pragma unroll
            for (int t = 0; t < 4; t++)
                rb[t] = *(const float4*)(Bg + (size_t)(k0 + bk)*COUT + bn + t*4);
        }

        #pragma unroll
        for (int ks = 0; ks < 2; ks++) {       // two k16 steps per BK=32 chunk
            uint32_t kOff = (uint32_t)(ks*16*2);
            uint32_t a0[4], a1[4];
            ldsm_x4(a0, aAddrBase + kOff);
            ldsm_x4(a1, aAddrBase + kOff + (uint32_t)(16*BKH*2));
            #pragma unroll
            for (int jj = 0; jj < 4; jj++) {   // pairs of n-octets
                uint32_t bb[4];
                ldsm_x4(bb, bAddrBase + kOff + (uint32_t)(jj*16*BKH*2));
                mma_f16(acc[0][2*jj],   a0, bb[0], bb[1]);
                mma_f16(acc[1][2*jj],   a1, bb[0], bb[1]);
                mma_f16(acc[0][2*jj+1], a0, bb[2], bb[3]);
                mma_f16(acc[1][2*jj+1], a1, bb[2], bb[3]);
            }
        }
        __syncthreads();
    }

    // epilogue: + cst, store, accumulate per-column BN2 stats
    float s[8][2], s2[8][2];
    #pragma unroll
    for (int j = 0; j < 8; j++) { s[j][0]=s[j][1]=s2[j][0]=s2[j][1]=0.f; }

    #pragma unroll
    for (int j = 0; j < 8; j++) {
        int col = colBase + wn*64 + j*8 + 2*(lane & 3);
        float2 cst2 = *(const float2*)&g_cst[col];
        #pragma unroll
        for (int i = 0; i < 2; i++) {
            int row0 = rowBase + wm*32 + i*16 + (lane >> 2);
            float z00 = acc[i][j][0] + cst2.x;
            float z01 = acc[i][j][1] + cst2.y;
            float z10 = acc[i][j][2] + cst2.x;
            float z11 = acc[i][j][3] + cst2.y;
            *(float2*)&C[(size_t)row0*COUT + col]       = make_float2(z00, z01);
            *(float2*)&C[(size_t)(row0 + 8)*COUT + col] = make_float2(z10, z11);
            s [j][0] += z00 + z10;         s [j][1] += z01 + z11;
            s2[j][0] += z00*z00 + z10*z10; s2[j][1] += z01*z01 + z11*z11;
        }
    }
    #pragma unroll
    for (int j = 0; j < 8; j++) {
        #pragma unroll
        for (int pr = 0; pr < 2; pr++) {
            float a = s[j][pr], b = s2[j][pr];
            #pragma unroll
            for (int off = 4; off <= 16; off <<= 1) {
                a += __shfl_xor_sync(0xffffffffu, a, off);
                b += __shfl_xor_sync(0xffffffffu, b, off);
            }
            if ((lane >> 2) == 0) {
                int col = colBase + wn*64 + j*8 + 2*(lane & 3) + pr;
                atomicAdd(&g_stats2[col],        a);
                atomicAdd(&g_stats2[COUT + col], b);
            }
        }
    }
}

// fused BN2-prep + affine + ReLU: each block recomputes ab2 into smem (identical
// deterministic values per block), then applies to its strided slice of z
__global__ void k_final(float* __restrict__ z, const float* __restrict__ gamma,
                        const float* __restrict__ beta) {
    __shared__ float sa[COUT], sb[COUT];
    int tid = threadIdx.x;
    #pragma unroll
    for (int q = 0; q < 2; q++) {
        int c = tid + q*256;
        float mean = g_stats2[c] / (float)MM;
        float var  = g_stats2[COUT + c] / (float)MM - mean * mean;
        float a = gamma[c] * rsqrtf(var + 1e-5f);
        sa[c] = a;
        sb[c] = beta[c] - mean * a;
    }
    __syncthreads();
    int idx = blockIdx.x * blockDim.x + tid;
    int stride = gridDim.x * blockDim.x;
    int n4 = MM * COUT / 4;
    for (int i = idx; i < n4; i += stride) {
        float4 v = ((float4*)z)[i];
        int o = (i * 4) & (COUT - 1);
        float4 a = *(const float4*)&sa[o];
        float4 b = *(const float4*)&sb[o];
        v.x = fmaxf(fmaf(a.x, v.x, b.x), 0.f);
        v.y = fmaxf(fmaf(a.y, v.y, b.y), 0.f);
        v.z = fmaxf(fmaf(a.z, v.z, b.z), 0.f);
        v.w = fmaxf(fmaf(a.w, v.w, b.w), 0.f);
        ((float4*)z)[i] = v;
    }
}

// ---------------- host launcher ------------------------------------------------

extern "C" void kernel_launch(void* const* d_in, const int* in_sizes, int n_in,
                              void* d_out, int out_size) {
    const float *x = nullptr, *loc = nullptr, *wt = nullptr;
    const float *dw = nullptr, *skipw = nullptr, *cw = nullptr;
    const float *g1 = nullptr, *b1 = nullptr, *g2 = nullptr, *b2 = nullptr;
    const int *ia = nullptr, *iat = nullptr;
    int c100352 = 0, c256 = 0, c512 = 0;
    for (int i = 0; i < n_in; i++) {
        int s = in_sizes[i];
        const void* p = d_in[i];
        if      (s == 12845056) x   = (const float*)p;
        else if (s == 200704)   loc = (const float*)p;
        else if (s == 100352) {
            if      (c100352 == 0) ia  = (const int*)p;     // idx_agg
            else if (c100352 == 1) { /* agg_weight: unused */ }
            else if (c100352 == 2) iat = (const int*)p;     // idx_agg_t
            else                   wt  = (const float*)p;   // agg_weight_t
            c100352++;
        }
        else if (s == 2304)   dw = (const float*)p;
        else if (s == 131072) cw = (const float*)p;
        else if (s == 256) {
            if      (c256 == 0) skipw = (const float*)p;
            else if (c256 == 1) g1    = (const float*)p;
            else                b1    = (const float*)p;
            c256++;
        }
        else if (s == 512) {
            if (c512 == 0) g2 = (const float*)p;
            else           b2 = (const float*)p;
            c512++;
        }
    }

    float* out = (float*)d_out;

    k_zero<<<1184, 256>>>();
    k_scatter<<<BB*NN0/8, 256>>>(x, loc, ia, iat, wt, skipw);
    k_conv<<<dim3(196, BB), 256>>>(dw);
    k_gather<<<BB*NN0/8, 256>>>(loc, iat, wt);
    k_fin1<<<1024, 256>>>();
    k_prepw<<<COUT, CIN>>>(cw, g1, b1);
    k_gemm<<<dim3(COUT/GBN, MM/GBM), 256>>>(out);
    k_final<<<1184, 256>>>(out, g2, b2);
}